// round 14
// baseline (speedup 1.0000x reference)
#include <cuda_runtime.h>
#include <math.h>

// Problem constants
#define BB   2
#define SS   2048
#define DD   1024
#define HH   16
#define HDIM 64
#define BHN  (BB*HH)   // 32

// Scratch for projected Q (pre-scaled by 0.125), K, V.
// Layout: [bh][s][e], each 2*16*2048*64 floats = 16 MB.
__device__ float g_Q[(size_t)BHN * SS * HDIM];
__device__ float g_K[(size_t)BHN * SS * HDIM];
__device__ float g_V[(size_t)BHN * SS * HDIM];

// ---------------------------------------------------------------------------
// QKV projection: per (b,h), X is the contiguous 2048x64 chunk
// x[bh*S*HD ...] (raw reshape semantics). q = X @ Wq^T + bq (then *0.125),
// k = X @ Wk^T + bk, v = X @ Wv^T + bv.
// Grid: (S/64, BH). 128 threads. Thread tile: 4 rows x 8 cols.
// ---------------------------------------------------------------------------
__global__ __launch_bounds__(128) void qkv_kernel(
    const float* __restrict__ x,
    const float* __restrict__ Wq, const float* __restrict__ bq,
    const float* __restrict__ Wk, const float* __restrict__ bk,
    const float* __restrict__ Wv, const float* __restrict__ bv)
{
    __shared__ float sX[64 * 68];   // X tile, [row][e], stride 68
    __shared__ float sWt[64 * 68];  // W transposed, [e][d], stride 68
    __shared__ float sb[64];

    const int tid = threadIdx.x;
    const int bh  = blockIdx.y;
    const int h   = bh & (HH - 1);
    const int s0  = blockIdx.x * 64;

    const float* xb = x + ((size_t)bh * SS + s0) * HDIM;

    // Load X tile (64x64) as float4
    for (int i = tid; i < 64 * 16; i += 128) {
        int r = i >> 4, f = (i & 15) * 4;
        *(float4*)(sX + r * 68 + f) = *(const float4*)(xb + r * HDIM + f);
    }

    const int ry = tid >> 3;   // 0..15 -> rows ry*4 .. ry*4+3
    const int cx = tid & 7;    // 0..7  -> cols cx*8 .. cx*8+7

    const float* Ws[3] = {Wq + h * HDIM * HDIM, Wk + h * HDIM * HDIM, Wv + h * HDIM * HDIM};
    const float* bs[3] = {bq + h * HDIM, bk + h * HDIM, bv + h * HDIM};
    float* outs[3] = {g_Q, g_K, g_V};

    for (int w = 0; w < 3; w++) {
        __syncthreads();  // protect sWt reuse (and covers X stores on first pass)
        const float* W = Ws[w];
        for (int i = tid; i < 64 * 64; i += 128) {
            int d = i >> 6, e = i & 63;
            sWt[e * 68 + d] = W[i];   // W[d][e] -> sWt[e][d]
        }
        if (tid < 64) sb[tid] = bs[w][tid];
        __syncthreads();

        float acc[4][8];
        #pragma unroll
        for (int i = 0; i < 4; i++)
            #pragma unroll
            for (int j = 0; j < 8; j++) acc[i][j] = 0.f;

        for (int e4 = 0; e4 < 16; e4++) {
            float4 xv[4];
            #pragma unroll
            for (int i = 0; i < 4; i++)
                xv[i] = *(const float4*)(sX + (ry * 4 + i) * 68 + e4 * 4);
            #pragma unroll
            for (int t = 0; t < 4; t++) {
                float4 w0 = *(const float4*)(sWt + (e4 * 4 + t) * 68 + cx * 8);
                float4 w1 = *(const float4*)(sWt + (e4 * 4 + t) * 68 + cx * 8 + 4);
                #pragma unroll
                for (int i = 0; i < 4; i++) {
                    float a = (t == 0) ? xv[i].x : (t == 1) ? xv[i].y : (t == 2) ? xv[i].z : xv[i].w;
                    acc[i][0] += a * w0.x; acc[i][1] += a * w0.y;
                    acc[i][2] += a * w0.z; acc[i][3] += a * w0.w;
                    acc[i][4] += a * w1.x; acc[i][5] += a * w1.y;
                    acc[i][6] += a * w1.z; acc[i][7] += a * w1.w;
                }
            }
        }

        const float qs = (w == 0) ? 0.125f : 1.0f;  // fold attention scale into Q
        float* og = outs[w] + ((size_t)bh * SS + s0) * HDIM;
        #pragma unroll
        for (int i = 0; i < 4; i++) {
            int r = ry * 4 + i;
            float4 o0, o1;
            o0.x = (acc[i][0] + sb[cx * 8 + 0]) * qs;
            o0.y = (acc[i][1] + sb[cx * 8 + 1]) * qs;
            o0.z = (acc[i][2] + sb[cx * 8 + 2]) * qs;
            o0.w = (acc[i][3] + sb[cx * 8 + 3]) * qs;
            o1.x = (acc[i][4] + sb[cx * 8 + 4]) * qs;
            o1.y = (acc[i][5] + sb[cx * 8 + 5]) * qs;
            o1.z = (acc[i][6] + sb[cx * 8 + 6]) * qs;
            o1.w = (acc[i][7] + sb[cx * 8 + 7]) * qs;
            *(float4*)(og + r * HDIM + cx * 8)     = o0;
            *(float4*)(og + r * HDIM + cx * 8 + 4) = o1;
        }
    }
}

// ---------------------------------------------------------------------------
// Flash attention: per (b,h), Q tile of 128 rows, stream K/V in 64-row tiles,
// online softmax. 128 threads, per-thread 8x8 register tiles.
// Output written as out[b, s, h*64 + d] (head-concat layout).
// Grid: (S/128, BH). Dynamic smem: 104448 B.
// ---------------------------------------------------------------------------
__global__ __launch_bounds__(128) void attn_kernel(float* __restrict__ out)
{
    extern __shared__ float sm[];
    float* sQ  = sm;                 // 128*68  [row][e]
    float* sKt = sQ  + 128 * 68;     // 64*68   [e][c]  (K transposed)
    float* sV  = sKt + 64 * 68;      // 64*68   [c][d]
    float* sP  = sV  + 64 * 68;      // 128*68  [row][c]

    const int tid = threadIdx.x;
    const int bh  = blockIdx.y;
    const int b   = bh >> 4;
    const int h   = bh & 15;
    const int q0  = blockIdx.x * 128;

    const float* Qg = g_Q + ((size_t)bh * SS + q0) * HDIM;
    const float* Kg = g_K + (size_t)bh * SS * HDIM;
    const float* Vg = g_V + (size_t)bh * SS * HDIM;

    // Load Q tile (128x64), already scaled by 0.125 at projection time
    for (int i = tid; i < 128 * 16; i += 128) {
        int r = i >> 4, f = (i & 15) * 4;
        *(float4*)(sQ + r * 68 + f) = *(const float4*)(Qg + r * HDIM + f);
    }

    const int ry = tid >> 3;   // rows ry*8 .. ry*8+7
    const int cx = tid & 7;    // cols cx*8 .. cx*8+7

    float m[8], l[8], o[8][8];
    #pragma unroll
    for (int i = 0; i < 8; i++) {
        m[i] = -1e30f;
        l[i] = 0.f;
        #pragma unroll
        for (int j = 0; j < 8; j++) o[i][j] = 0.f;
    }

    for (int kv = 0; kv < SS; kv += 64) {
        __syncthreads();  // previous iteration done with sKt/sV/sP (also covers sQ on iter 0)

        // Load K (transposed into sKt) and V (natural) for this 64-key tile
        for (int i = tid; i < 64 * 16; i += 128) {
            int r = i >> 4, f = (i & 15) * 4;
            float4 kq = *(const float4*)(Kg + (size_t)(kv + r) * HDIM + f);
            sKt[(f + 0) * 68 + r] = kq.x;
            sKt[(f + 1) * 68 + r] = kq.y;
            sKt[(f + 2) * 68 + r] = kq.z;
            sKt[(f + 3) * 68 + r] = kq.w;
            *(float4*)(sV + r * 68 + f) = *(const float4*)(Vg + (size_t)(kv + r) * HDIM + f);
        }
        __syncthreads();

        // ---- S = Q @ K^T (scale pre-folded into Q) ----
        float sacc[8][8];
        #pragma unroll
        for (int i = 0; i < 8; i++)
            #pragma unroll
            for (int j = 0; j < 8; j++) sacc[i][j] = 0.f;

        for (int e4 = 0; e4 < 16; e4++) {
            float4 qv[8];
            #pragma unroll
            for (int i = 0; i < 8; i++)
                qv[i] = *(const float4*)(sQ + (ry * 8 + i) * 68 + e4 * 4);
            #pragma unroll
            for (int t = 0; t < 4; t++) {
                float4 k0 = *(const float4*)(sKt + (e4 * 4 + t) * 68 + cx * 8);
                float4 k1 = *(const float4*)(sKt + (e4 * 4 + t) * 68 + cx * 8 + 4);
                #pragma unroll
                for (int i = 0; i < 8; i++) {
                    float a = (t == 0) ? qv[i].x : (t == 1) ? qv[i].y : (t == 2) ? qv[i].z : qv[i].w;
                    sacc[i][0] += a * k0.x; sacc[i][1] += a * k0.y;
                    sacc[i][2] += a * k0.z; sacc[i][3] += a * k0.w;
                    sacc[i][4] += a * k1.x; sacc[i][5] += a * k1.y;
                    sacc[i][6] += a * k1.z; sacc[i][7] += a * k1.w;
                }
            }
        }

        // ---- online softmax (row groups of 8 lanes share a row) ----
        #pragma unroll
        for (int i = 0; i < 8; i++) {
            float tm = sacc[i][0];
            #pragma unroll
            for (int j = 1; j < 8; j++) tm = fmaxf(tm, sacc[i][j]);
            #pragma unroll
            for (int off = 1; off < 8; off <<= 1)
                tm = fmaxf(tm, __shfl_xor_sync(0xffffffffu, tm, off));

            float mn    = fmaxf(m[i], tm);
            float alpha = __expf(m[i] - mn);
            m[i] = mn;

            float rs = 0.f;
            #pragma unroll
            for (int j = 0; j < 8; j++) {
                float p = __expf(sacc[i][j] - mn);
                sacc[i][j] = p;
                rs += p;
            }
            #pragma unroll
            for (int off = 1; off < 8; off <<= 1)
                rs += __shfl_xor_sync(0xffffffffu, rs, off);

            l[i] = l[i] * alpha + rs;
            #pragma unroll
            for (int j = 0; j < 8; j++) o[i][j] *= alpha;

            *(float4*)(sP + (ry * 8 + i) * 68 + cx * 8) =
                make_float4(sacc[i][0], sacc[i][1], sacc[i][2], sacc[i][3]);
            *(float4*)(sP + (ry * 8 + i) * 68 + cx * 8 + 4) =
                make_float4(sacc[i][4], sacc[i][5], sacc[i][6], sacc[i][7]);
        }
        __syncthreads();

        // ---- O += P @ V ----
        for (int c4 = 0; c4 < 16; c4++) {
            float4 pv[8];
            #pragma unroll
            for (int i = 0; i < 8; i++)
                pv[i] = *(const float4*)(sP + (ry * 8 + i) * 68 + c4 * 4);
            #pragma unroll
            for (int t = 0; t < 4; t++) {
                float4 v0 = *(const float4*)(sV + (c4 * 4 + t) * 68 + cx * 8);
                float4 v1 = *(const float4*)(sV + (c4 * 4 + t) * 68 + cx * 8 + 4);
                #pragma unroll
                for (int i = 0; i < 8; i++) {
                    float a = (t == 0) ? pv[i].x : (t == 1) ? pv[i].y : (t == 2) ? pv[i].z : pv[i].w;
                    o[i][0] += a * v0.x; o[i][1] += a * v0.y;
                    o[i][2] += a * v0.z; o[i][3] += a * v0.w;
                    o[i][4] += a * v1.x; o[i][5] += a * v1.y;
                    o[i][6] += a * v1.z; o[i][7] += a * v1.w;
                }
            }
        }
    }

    // ---- epilogue: normalize and write out[b, s, h*64 + d] ----
    float* ob = out + ((size_t)b * SS + q0) * DD + h * HDIM;
    #pragma unroll
    for (int i = 0; i < 8; i++) {
        int r = ry * 8 + i;
        float inv = 1.0f / l[i];
        float4 w0 = make_float4(o[i][0] * inv, o[i][1] * inv, o[i][2] * inv, o[i][3] * inv);
        float4 w1 = make_float4(o[i][4] * inv, o[i][5] * inv, o[i][6] * inv, o[i][7] * inv);
        *(float4*)(ob + (size_t)r * DD + cx * 8)     = w0;
        *(float4*)(ob + (size_t)r * DD + cx * 8 + 4) = w1;
    }
}

// ---------------------------------------------------------------------------
// kernel_launch: graph-capturable, allocation-free.
// Inputs (metadata order): x, Wq, bq, Wk, bk, Wv, bv — all float32.
// ---------------------------------------------------------------------------
extern "C" void kernel_launch(void* const* d_in, const int* in_sizes, int n_in,
                              void* d_out, int out_size)
{
    (void)in_sizes; (void)n_in; (void)out_size;
    const float* x  = (const float*)d_in[0];
    const float* Wq = (const float*)d_in[1];
    const float* bq = (const float*)d_in[2];
    const float* Wk = (const float*)d_in[3];
    const float* bk = (const float*)d_in[4];
    const float* Wv = (const float*)d_in[5];
    const float* bv = (const float*)d_in[6];
    float* out = (float*)d_out;

    qkv_kernel<<<dim3(SS / 64, BHN), 128>>>(x, Wq, bq, Wk, bk, Wv, bv);

    const int smem_bytes = (128 * 68 + 64 * 68 + 64 * 68 + 128 * 68) * (int)sizeof(float);
    cudaFuncSetAttribute(attn_kernel, cudaFuncAttributeMaxDynamicSharedMemorySize, smem_bytes);
    attn_kernel<<<dim3(SS / 128, BHN), 128, smem_bytes>>>(out);
}